// round 13
// baseline (speedup 1.0000x reference)
#include <cuda_runtime.h>
#include <stdint.h>

#define NTOK  8192      // BATCH * SEQ
#define D     256       // EMBED_DIM
#define NR    100       // NUM_RULES
#define COLT  32        // output-column tile per block (32 KB M tile -> 3 blocks/SM)
#define TT    32        // token tile per iteration
#define KC    4         // token-chunk grid dimension (load balancing)
#define BPAD  260       // padded base row stride (floats)

// ---------------- scratch (device globals; no allocation allowed) ----------------
__device__ int g_offset[NR + 1];
__device__ int g_bucket[NTOK];   // token flat-indices grouped by rule

// ---------------- fused bucketing: histogram + scan + scatter in ONE block ----------------
__global__ __launch_bounds__(1024, 1)
void k_bucket(const int* __restrict__ token_ids,
              const int* __restrict__ token_rules) {
    __shared__ int s_cnt[NR];    // histogram, then reused as scatter cursor
    __shared__ int s_off[NR];    // exclusive offsets
    const int tid = threadIdx.x;

    if (tid < NR) s_cnt[tid] = 0;
    __syncthreads();

    int rl[8];
    #pragma unroll
    for (int j = 0; j < 8; ++j) {
        int i = tid + j * 1024;
        rl[j] = token_rules[token_ids[i]];
    }
    #pragma unroll
    for (int j = 0; j < 8; ++j) atomicAdd(&s_cnt[rl[j]], 1);
    __syncthreads();

    if (tid == 0) {
        int acc = 0;
        for (int r = 0; r < NR; ++r) {
            s_off[r] = acc;
            g_offset[r] = acc;
            acc += s_cnt[r];
        }
        g_offset[NR] = acc;
    }
    __syncthreads();

    if (tid < NR) s_cnt[tid] = s_off[tid];
    __syncthreads();

    #pragma unroll
    for (int j = 0; j < 8; ++j) {
        int i = tid + j * 1024;
        int p = atomicAdd(&s_cnt[rl[j]], 1);
        g_bucket[p] = i;
    }
}

// ---------------- per-rule batched GEMM ----------------
// grid: (D/COLT=8, NR, KC). block: 128 threads = 16 rowgroups x 8 colgroups.
// Each thread: 2 tokens x 4 cols, packed fma.rn.f32x2.
// smem: sM [256][32] f32 (32KB) + sB [32][BPAD] f32 (~33.3KB) = 66KB
// -> 3 blocks/SM = 12 warps/SM. m-LDS.128 = 1 wavefront (each 8-thread phase
// reads one 128B row = full bank sweep, conflict-free); b-LDS.128 broadcast
// over 4 bank-disjoint rows = 1 wavefront.
// Model: LSU/crossbar ceilings ~170 FMA/cyc/SM > FFMA2 pipe 128 -> pipe-bound.
__global__ __launch_bounds__(128, 3)
void k_gemm(const int* __restrict__ token_ids,
            const float* __restrict__ base,
            const float* __restrict__ rules,
            float* __restrict__ out) {
    const int r   = blockIdx.y;
    const int c0  = blockIdx.x * COLT;
    const int off = g_offset[r];
    const int n   = g_offset[r + 1] - off;
    const int tstart = (int)blockIdx.z * TT;
    if (tstart >= n) return;   // empty chunk lane: exit before any smem work

    extern __shared__ float sm[];
    float* sM = sm;                 // [256][32]
    float* sB = sm + D * COLT;      // [32][BPAD]
    const int tid = threadIdx.x;

    // Load M[r][:, c0:c0+32] into smem. Coalesced float4 loads. 16 iters/thread.
    const float* Mg = rules + (size_t)r * D * D + c0;
    #pragma unroll
    for (int i = tid; i < D * (COLT / 4); i += 128) {
        int d = i >> 3, v = i & 7;
        *(float4*)(sM + d * COLT + v * 4) = *(const float4*)(Mg + (size_t)d * D + v * 4);
    }
    __syncthreads();

    const int row = tid >> 3;         // 0..15
    const int cg  = (tid & 7) * 4;    // 0,4,...,28
    const int t00 = row * 2;          // first of 2 tokens for this thread

    for (int t0 = tstart; t0 < n; t0 += KC * TT) {
        const int nt = min(TT, n - t0);
        __syncthreads();  // previous tile's readers done before overwriting sB

        // Gather up to 32 token embeddings into padded smem rows. 16 iters/thread.
        for (int i = tid; i < TT * (D / 4); i += 128) {
            int tk = i >> 6, v = i & 63;
            float4 val = make_float4(0.f, 0.f, 0.f, 0.f);
            if (tk < nt) {
                int flat = g_bucket[off + t0 + tk];
                int tok  = token_ids[flat];
                val = *(const float4*)(base + (size_t)tok * D + v * 4);
            }
            *(float4*)(sB + tk * BPAD + v * 4) = val;
        }
        __syncthreads();

        // acc[j] = {col pair 0 (m.x), col pair 1 (m.y)} for token t00+j
        unsigned long long acc[2][2];
        acc[0][0] = 0ULL; acc[0][1] = 0ULL;
        acc[1][0] = 0ULL; acc[1][1] = 0ULL;

        const float* b0 = sB + (t00 + 0) * BPAD;
        const float* b1 = sB + (t00 + 1) * BPAD;

        #pragma unroll 2
        for (int d = 0; d < D; d += 4) {
            float4 v0 = *(const float4*)(b0 + d);
            float4 v1 = *(const float4*)(b1 + d);
            #pragma unroll
            for (int u = 0; u < 4; ++u) {
                ulonglong2 m = *(const ulonglong2*)(sM + (d + u) * COLT + cg);
                float f0 = (u == 0) ? v0.x : (u == 1) ? v0.y : (u == 2) ? v0.z : v0.w;
                float f1 = (u == 0) ? v1.x : (u == 1) ? v1.y : (u == 2) ? v1.z : v1.w;
                unsigned int s0 = __float_as_uint(f0), s1 = __float_as_uint(f1);
                unsigned long long p0, p1;
                asm("mov.b64 %0, {%1,%1};" : "=l"(p0) : "r"(s0));
                asm("mov.b64 %0, {%1,%1};" : "=l"(p1) : "r"(s1));
                asm("fma.rn.f32x2 %0, %1, %2, %0;" : "+l"(acc[0][0]) : "l"(m.x), "l"(p0));
                asm("fma.rn.f32x2 %0, %1, %2, %0;" : "+l"(acc[0][1]) : "l"(m.y), "l"(p0));
                asm("fma.rn.f32x2 %0, %1, %2, %0;" : "+l"(acc[1][0]) : "l"(m.x), "l"(p1));
                asm("fma.rn.f32x2 %0, %1, %2, %0;" : "+l"(acc[1][1]) : "l"(m.y), "l"(p1));
            }
        }

        #pragma unroll
        for (int j = 0; j < 2; ++j) {
            int t = t00 + j;
            if (t < nt) {
                int flat = g_bucket[off + t0 + t];
                unsigned int lo, hi;
                float4 v;
                asm("mov.b64 {%0,%1}, %2;" : "=r"(lo), "=r"(hi) : "l"(acc[j][0]));
                v.x = __uint_as_float(lo); v.y = __uint_as_float(hi);
                asm("mov.b64 {%0,%1}, %2;" : "=r"(lo), "=r"(hi) : "l"(acc[j][1]));
                v.z = __uint_as_float(lo); v.w = __uint_as_float(hi);
                *(float4*)(out + (size_t)flat * D + c0 + cg) = v;
            }
        }
    }
}

// ---------------- launch: 2 kernels total ----------------
extern "C" void kernel_launch(void* const* d_in, const int* in_sizes, int n_in,
                              void* d_out, int out_size) {
    const int*   token_ids   = (const int*)d_in[0];    // [4,2048] int32
    const float* base        = (const float*)d_in[1];  // [32000,256] f32
    const float* rules       = (const float*)d_in[2];  // [100,256,256] f32
    const int*   token_rules = (const int*)d_in[3];    // [32000] int32
    float*       out         = (float*)d_out;          // [4,2048,256] f32

    const int SMEM = (D * COLT + TT * BPAD) * (int)sizeof(float);  // 66048 B
    cudaFuncSetAttribute(k_gemm, cudaFuncAttributeMaxDynamicSharedMemorySize, SMEM);

    k_bucket<<<1, 1024>>>(token_ids, token_rules);
    k_gemm<<<dim3(D / COLT, NR, KC), 128, SMEM>>>(token_ids, base, rules, out);
}

// round 15
// speedup vs baseline: 1.0589x; 1.0589x over previous
#include <cuda_runtime.h>
#include <stdint.h>

#define NTOK  8192      // BATCH * SEQ
#define D     256       // EMBED_DIM
#define NR    100       // NUM_RULES
#define COLT  64        // output-column tile per block (64 KB M tile, only smem user)
#define TT    32        // token tile per iteration
#define KC    4         // token-chunk grid dimension (load balancing)

// ---------------- scratch (device globals; no allocation allowed) ----------------
__device__ int g_offset[NR + 1];
__device__ int g_bucket[NTOK];   // token flat-indices grouped by rule

// ---------------- fused bucketing: histogram + scan + scatter in ONE block ----------------
__global__ __launch_bounds__(1024, 1)
void k_bucket(const int* __restrict__ token_ids,
              const int* __restrict__ token_rules) {
    __shared__ int s_cnt[NR];    // histogram, then reused as scatter cursor
    __shared__ int s_off[NR];    // exclusive offsets
    const int tid = threadIdx.x;

    if (tid < NR) s_cnt[tid] = 0;
    __syncthreads();

    int rl[8];
    #pragma unroll
    for (int j = 0; j < 8; ++j) {
        int i = tid + j * 1024;
        rl[j] = token_rules[token_ids[i]];
    }
    #pragma unroll
    for (int j = 0; j < 8; ++j) atomicAdd(&s_cnt[rl[j]], 1);
    __syncthreads();

    if (tid == 0) {
        int acc = 0;
        for (int r = 0; r < NR; ++r) {
            s_off[r] = acc;
            g_offset[r] = acc;
            acc += s_cnt[r];
        }
        g_offset[NR] = acc;
    }
    __syncthreads();

    if (tid < NR) s_cnt[tid] = s_off[tid];
    __syncthreads();

    #pragma unroll
    for (int j = 0; j < 8; ++j) {
        int i = tid + j * 1024;
        int p = atomicAdd(&s_cnt[rl[j]], 1);
        g_bucket[p] = i;
    }
}

// ---------------- per-rule batched GEMM ----------------
// grid: (D/COLT=4, NR, KC). block: 128 threads = 16 rowgroups x 8 colgroups.
// Each thread: 2 tokens x 8 cols (two quads at cg4 and cg4+32), fma.rn.f32x2.
// Embeddings (b) read DIRECTLY from global (L1-cached) -> no sB, no per-tile
// barriers; smem = sM only (64 KB) -> 3 blocks/SM = 12 warps/SM.
// m LDS.128: 8 lanes x 16B contiguous per phase row -> 1 wavefront, conflict-free.
__global__ __launch_bounds__(128, 3)
void k_gemm(const int* __restrict__ token_ids,
            const float* __restrict__ base,
            const float* __restrict__ rules,
            float* __restrict__ out) {
    const int r   = blockIdx.y;
    const int c0  = blockIdx.x * COLT;
    const int off = g_offset[r];
    const int n   = g_offset[r + 1] - off;
    const int tstart = (int)blockIdx.z * TT;
    if (tstart >= n) return;   // empty chunk lane

    extern __shared__ float sM[];   // [256][64]
    const int tid = threadIdx.x;

    // Load M[r][:, c0:c0+64] into smem. Coalesced float4 loads. 32 iters/thread.
    const float* Mg = rules + (size_t)r * D * D + c0;
    #pragma unroll
    for (int i = tid; i < D * (COLT / 4); i += 128) {
        int d = i >> 4, v = i & 15;
        *(float4*)(sM + d * COLT + v * 4) = *(const float4*)(Mg + (size_t)d * D + v * 4);
    }
    __syncthreads();

    const int row = tid >> 3;          // 0..15
    const int cg4 = (tid & 7) * 4;     // first quad: cols cg4..cg4+3; second: +32
    const int t00 = row * 2;

    for (int t0 = tstart; t0 < n; t0 += KC * TT) {
        const int nt = min(TT, n - t0);

        // per-thread token indices (clamped for safety; stores guarded)
        const int v0 = (t00 + 0 < nt);
        const int v1 = (t00 + 1 < nt);
        const int flat0 = g_bucket[off + t0 + (v0 ? t00 + 0 : 0)];
        const int flat1 = g_bucket[off + t0 + (v1 ? t00 + 1 : 0)];
        const float* bp0 = base + (size_t)token_ids[flat0] * D;
        const float* bp1 = base + (size_t)token_ids[flat1] * D;

        // acc[tok][pair]: 4 f32x2 col-pairs per token (cols cg4..+3, cg4+32..+35)
        unsigned long long acc[2][4];
        #pragma unroll
        for (int j = 0; j < 2; ++j)
            #pragma unroll
            for (int p = 0; p < 4; ++p) acc[j][p] = 0ULL;

        #pragma unroll 2
        for (int d = 0; d < D; d += 4) {
            float4 vb0 = *(const float4*)(bp0 + d);   // direct LDG, L1-cached
            float4 vb1 = *(const float4*)(bp1 + d);
            #pragma unroll
            for (int u = 0; u < 4; ++u) {
                const float* mrow = sM + (d + u) * COLT;
                ulonglong2 ma = *(const ulonglong2*)(mrow + cg4);        // cols cg4..cg4+3
                ulonglong2 mb = *(const ulonglong2*)(mrow + cg4 + 32);   // cols +32..+35
                float f0 = (u == 0) ? vb0.x : (u == 1) ? vb0.y : (u == 2) ? vb0.z : vb0.w;
                float f1 = (u == 0) ? vb1.x : (u == 1) ? vb1.y : (u == 2) ? vb1.z : vb1.w;
                unsigned int s0 = __float_as_uint(f0), s1 = __float_as_uint(f1);
                unsigned long long p0, p1;
                asm("mov.b64 %0, {%1,%1};" : "=l"(p0) : "r"(s0));
                asm("mov.b64 %0, {%1,%1};" : "=l"(p1) : "r"(s1));
                asm("fma.rn.f32x2 %0, %1, %2, %0;" : "+l"(acc[0][0]) : "l"(ma.x), "l"(p0));
                asm("fma.rn.f32x2 %0, %1, %2, %0;" : "+l"(acc[0][1]) : "l"(ma.y), "l"(p0));
                asm("fma.rn.f32x2 %0, %1, %2, %0;" : "+l"(acc[0][2]) : "l"(mb.x), "l"(p0));
                asm("fma.rn.f32x2 %0, %1, %2, %0;" : "+l"(acc[0][3]) : "l"(mb.y), "l"(p0));
                asm("fma.rn.f32x2 %0, %1, %2, %0;" : "+l"(acc[1][0]) : "l"(ma.x), "l"(p1));
                asm("fma.rn.f32x2 %0, %1, %2, %0;" : "+l"(acc[1][1]) : "l"(ma.y), "l"(p1));
                asm("fma.rn.f32x2 %0, %1, %2, %0;" : "+l"(acc[1][2]) : "l"(mb.x), "l"(p1));
                asm("fma.rn.f32x2 %0, %1, %2, %0;" : "+l"(acc[1][3]) : "l"(mb.y), "l"(p1));
            }
        }

        #pragma unroll
        for (int j = 0; j < 2; ++j) {
            if (j == 0 ? v0 : v1) {
                int flat = (j == 0) ? flat0 : flat1;
                unsigned int lo, hi;
                float4 va, vb;
                asm("mov.b64 {%0,%1}, %2;" : "=r"(lo), "=r"(hi) : "l"(acc[j][0]));
                va.x = __uint_as_float(lo); va.y = __uint_as_float(hi);
                asm("mov.b64 {%0,%1}, %2;" : "=r"(lo), "=r"(hi) : "l"(acc[j][1]));
                va.z = __uint_as_float(lo); va.w = __uint_as_float(hi);
                asm("mov.b64 {%0,%1}, %2;" : "=r"(lo), "=r"(hi) : "l"(acc[j][2]));
                vb.x = __uint_as_float(lo); vb.y = __uint_as_float(hi);
                asm("mov.b64 {%0,%1}, %2;" : "=r"(lo), "=r"(hi) : "l"(acc[j][3]));
                vb.z = __uint_as_float(lo); vb.w = __uint_as_float(hi);
                float* op = out + (size_t)flat * D + c0 + cg4;
                *(float4*)op        = va;
                *(float4*)(op + 32) = vb;
            }
        }
    }
}

// ---------------- launch: 2 kernels total ----------------
extern "C" void kernel_launch(void* const* d_in, const int* in_sizes, int n_in,
                              void* d_out, int out_size) {
    const int*   token_ids   = (const int*)d_in[0];    // [4,2048] int32
    const float* base        = (const float*)d_in[1];  // [32000,256] f32
    const float* rules       = (const float*)d_in[2];  // [100,256,256] f32
    const int*   token_rules = (const int*)d_in[3];    // [32000] int32
    float*       out         = (float*)d_out;          // [4,2048,256] f32

    const int SMEM = D * COLT * (int)sizeof(float);    // 65536 B
    cudaFuncSetAttribute(k_gemm, cudaFuncAttributeMaxDynamicSharedMemorySize, SMEM);

    k_bucket<<<1, 1024>>>(token_ids, token_rules);
    k_gemm<<<dim3(D / COLT, NR, KC), 128, SMEM>>>(token_ids, base, rules, out);
}